// round 16
// baseline (speedup 1.0000x reference)
#include <cuda_runtime.h>
#include <cuda_fp16.h>
#include <cstdint>

typedef unsigned long long ull;

#define EMB 128
#define INT_EMB 64
#define NRAD 6
#define NSR 42
#define BASIS 8
#define E_EDGES 262144
#define T_TRIP 2097152

// ---------------- scratch (device globals) ------------------------------------
__device__ float g_Wr[NRAD*EMB];
__device__ float g_xji[(size_t)E_EDGES*EMB];
__device__ float g_tmp[(size_t)E_EDGES*EMB];
__device__ float g_upd[(size_t)E_EDGES*EMB];
__device__ float g_xkj2[(size_t)E_EDGES*INT_EMB];
__device__ float g_agg[(size_t)E_EDGES*INT_EMB];
__device__ uint32_t g_Bh[81920];   // all weights, fp16 fragment layout (m16n8k16)

// B-frag offsets (u32 elements; 128x128 matrix = 8192 u32)
#define OFF_JI   0
#define OFF_KJ   8192
#define OFF_DOWN 16384
#define OFF_UP   20480
#define OFF_B1   24576
#define OFF_B2   32768
#define OFF_FIN  40960
#define OFF_A10  49152
#define OFF_A20  57344
#define OFF_A11  65536
#define OFF_A21  73728

// ---------------- helpers ------------------------------------------------------
__device__ __forceinline__ float silu_f(float x){ return x * (1.0f/(1.0f + __expf(-x))); }
__device__ __forceinline__ uint32_t pack_h2(float lo, float hi){
    __half2 h = __floats2half2_rn(lo, hi);
    return *(uint32_t*)&h;
}
__device__ __forceinline__ void mma_f16(float* c, const uint32_t* a, const uint32_t* b){
    asm volatile("mma.sync.aligned.m16n8k16.row.col.f32.f16.f16.f32 "
        "{%0,%1,%2,%3}, {%4,%5,%6,%7}, {%8,%9}, {%0,%1,%2,%3};"
        : "+f"(c[0]), "+f"(c[1]), "+f"(c[2]), "+f"(c[3])
        : "r"(a[0]), "r"(a[1]), "r"(a[2]), "r"(a[3]), "r"(b[0]), "r"(b[1]));
}

// ---------------- K0: fuse W_rbf1 @ W_rbf2 -> g_Wr ----------------------------
__global__ void fuse_wr_kernel(const float* __restrict__ W1, const float* __restrict__ W2) {
    int i = blockIdx.x * blockDim.x + threadIdx.x;
    if (i < NRAD * EMB) {
        int r = i / EMB, n = i % EMB;
        float s = 0.f;
#pragma unroll
        for (int b = 0; b < BASIS; b++) s += W1[r*BASIS + b] * W2[b*EMB + n];
        g_Wr[i] = s;
    }
}

// ---------------- zero g_agg --------------------------------------------------
__global__ void zero_agg_kernel() {
    size_t i = (size_t)blockIdx.x * blockDim.x + threadIdx.x;
    float4 z = {0.f, 0.f, 0.f, 0.f};
    ((float4*)g_agg)[i] = z;
}

// ---------------- B fragment precompute (fp16 m16n8k16 layout) ------------------
__global__ void stage_Bh(const float* __restrict__ W, uint32_t* __restrict__ out,
                         int K, int N) {
    int i = blockIdx.x * 128 + threadIdx.x;
    if (i >= (K/2)*N) return;
    int kp = i / N, n = i % N;
    int k = kp * 2;
    uint32_t h = pack_h2(W[(size_t)k*N + n], W[(size_t)(k+1)*N + n]);
    int NT = N/8;
    int s = k >> 4, kk = k & 15;
    int rg = kk >> 3, lp = (kk & 7) >> 1;
    int lane = ((n & 7) << 2) | lp;
    int nt = n >> 3;
    out[((s*NT + nt)*32 + lane)*2 + rg] = h;
}

// ---------------- A staging: fp16 pairs, row-major, XOR-swizzled ----------------
template<int K>
__device__ __forceinline__ void stage_Ah(const float* __restrict__ A, size_t m0,
                                         uint32_t* __restrict__ As, int tid) {
    constexpr int QPR = K/4, RW = K/2;
    for (int i = tid; i < 128*QPR; i += 256) {
        int row = i / QPR, q4 = i % QPR;
        const float4 a4 = *(const float4*)&A[(m0+row)*K + q4*4];
        uint2 t;
        t.x = pack_h2(a4.x, a4.y);
        t.y = pack_h2(a4.z, a4.w);
        int c = (q4*2) ^ ((row & 7) << 2);
        *(uint2*)&As[row*RW + c] = t;
    }
}

// ---------------- async full-matrix copy (gmem frags -> smem) -------------------
template<int WORDS>
__device__ __forceinline__ void cp_all(uint32_t* __restrict__ Bs,
                                       const uint32_t* __restrict__ Bf, int tid) {
    constexpr int NCP = (WORDS*4) / (256*16);
    const uint32_t sdst = (uint32_t)__cvta_generic_to_shared(Bs);
#pragma unroll
    for (int i = 0; i < NCP; i++) {
        const int off = (tid + i*256) * 16;
        asm volatile("cp.async.cg.shared.global [%0], [%1], 16;"
            :: "r"(sdst + (uint32_t)off), "l"((const char*)Bf + off) : "memory");
    }
}
#define CP_COMMIT() asm volatile("cp.async.commit_group;" ::: "memory")
#define CP_WAIT0()  asm volatile("cp.async.wait_group 0;" ::: "memory")

// ---------------- barrier-free mainloop: all of A and B resident in SMEM --------
template<int K, int NT, int WNT>
__device__ __forceinline__ void mainloop_full(const uint32_t* __restrict__ As,
                                              const uint32_t* __restrict__ Bs,
                                              int mp, int nt0, int lane,
                                              float (*acc0)[4], float (*acc1)[4]) {
    constexpr int KS = K/16, RW = K/2;
    const int q = lane >> 2, sw = q << 2;
    const int rowA0 = (mp*32 + q) * RW;
    const int rowA1 = rowA0 + 16*RW;
#pragma unroll
    for (int s = 0; s < KS; s++) {
        const int cb = s*8 + (lane & 3);
        uint32_t a[2][4];
        a[0][0] = As[rowA0        + (cb ^ sw)];
        a[0][1] = As[rowA0 + 8*RW + (cb ^ sw)];
        a[0][2] = As[rowA0        + ((cb+4) ^ sw)];
        a[0][3] = As[rowA0 + 8*RW + ((cb+4) ^ sw)];
        a[1][0] = As[rowA1        + (cb ^ sw)];
        a[1][1] = As[rowA1 + 8*RW + (cb ^ sw)];
        a[1][2] = As[rowA1        + ((cb+4) ^ sw)];
        a[1][3] = As[rowA1 + 8*RW + ((cb+4) ^ sw)];
#pragma unroll
        for (int j = 0; j < WNT; j++) {
            uint2 b = *(const uint2*)&Bs[((s*NT + nt0 + j)*32 + lane)*2];
            mma_f16(acc0[j], a[0], (const uint32_t*)&b);
            mma_f16(acc1[j], a[1], (const uint32_t*)&b);
        }
    }
}
template<int W4>
__device__ __forceinline__ void zero_acc(float (*acc)[4]) {
#pragma unroll
    for (int i = 0; i < W4; i++)
#pragma unroll
        for (int e = 0; e < 4; e++) acc[i][e] = 0.f;
}

// ---------------- generic fused GEMM -------------------------------------------
template<int N, int K, bool MUL_RBF, bool ADD_RES>
__global__ __launch_bounds__(256, 2)
void gemm_h(const float* __restrict__ A, const uint32_t* __restrict__ Bf,
            const float* __restrict__ bias, const float* __restrict__ res,
            const float* __restrict__ rbf, float* __restrict__ out) {
    constexpr int NT = N/8, WNT = NT/2;
    constexpr int BW = (K/16)*NT*64;
    extern __shared__ __align__(16) uint32_t dyn[];
    uint32_t* As = dyn;
    uint32_t* Bs = dyn + 128*(K/2);
    __shared__ float s_Wr[MUL_RBF ? NRAD*EMB : 1];

    const int tid = threadIdx.x, lane = tid & 31, w = tid >> 5;
    const size_t m0 = (size_t)blockIdx.x * 128;
    const int mp = w >> 1;
    const int nt0 = (w & 1) * WNT;
    const int q = lane >> 2;

    cp_all<BW>(Bs, Bf, tid);
    CP_COMMIT();
    if (MUL_RBF) for (int i = tid; i < NRAD*EMB; i += 256) s_Wr[i] = g_Wr[i];
    stage_Ah<K>(A, m0, As, tid);
    CP_WAIT0();
    __syncthreads();

    float acc[2][WNT][4];
    zero_acc<2*WNT>(&acc[0][0]);
    mainloop_full<K, NT, WNT>(As, Bs, mp, nt0, lane, acc[0], acc[1]);

#pragma unroll
    for (int i = 0; i < 2; i++) {
        const size_t r_lo = m0 + mp*32 + i*16 + q;
        const size_t r_hi = r_lo + 8;
        float r6lo[NRAD], r6hi[NRAD];
        if (MUL_RBF) {
#pragma unroll
            for (int l = 0; l < NRAD; l++) { r6lo[l] = rbf[r_lo*NRAD + l]; r6hi[l] = rbf[r_hi*NRAD + l]; }
        }
#pragma unroll
        for (int j = 0; j < WNT; j++) {
            const int col = (nt0 + j)*8 + (lane & 3)*2;
            float2 bj = make_float2(0.f, 0.f);
            if (bias) bj = *(const float2*)&bias[col];
            float v00 = silu_f(acc[i][j][0] + bj.x);
            float v01 = silu_f(acc[i][j][1] + bj.y);
            float v10 = silu_f(acc[i][j][2] + bj.x);
            float v11 = silu_f(acc[i][j][3] + bj.y);
            if (MUL_RBF) {
                float e00=0.f,e01=0.f,e10=0.f,e11=0.f;
#pragma unroll
                for (int l = 0; l < NRAD; l++) {
                    const float w0 = s_Wr[l*EMB + col], w1 = s_Wr[l*EMB + col + 1];
                    e00 += r6lo[l]*w0; e01 += r6lo[l]*w1;
                    e10 += r6hi[l]*w0; e11 += r6hi[l]*w1;
                }
                v00 *= e00; v01 *= e01; v10 *= e10; v11 *= e11;
            }
            if (ADD_RES) {
                const float2 rl = *(const float2*)&res[r_lo*N + col];
                const float2 rh = *(const float2*)&res[r_hi*N + col];
                v00 += rl.x; v01 += rl.y; v10 += rh.x; v11 += rh.y;
            }
            float2 o0; o0.x = v00; o0.y = v01;
            float2 o1; o1.x = v10; o1.y = v11;
            *(float2*)&out[r_lo*N + col] = o0;
            *(float2*)&out[r_hi*N + col] = o1;
        }
    }
}

// ---------------- fused ji+kj kernel (both B matrices resident) -----------------
__global__ __launch_bounds__(256, 2)
void gemm2_h(const float* __restrict__ m,
             const uint32_t* __restrict__ Bf_ji, const uint32_t* __restrict__ Bf_kj,
             const float* __restrict__ b_ji, const float* __restrict__ b_kj,
             const float* __restrict__ rbf,
             float* __restrict__ out_ji, float* __restrict__ out_kj) {
    constexpr int NT = 16, WNT = 8, BW = 8192;
    extern __shared__ __align__(16) uint32_t dyn[];
    uint32_t* As  = dyn;            // 8192 u32
    uint32_t* Bs1 = dyn + 8192;     // 8192 u32
    uint32_t* Bs2 = dyn + 16384;    // 8192 u32
    __shared__ float s_Wr[NRAD*EMB];

    const int tid = threadIdx.x, lane = tid & 31, w = tid >> 5;
    const size_t m0 = (size_t)blockIdx.x * 128;
    const int mp = w >> 1;
    const int nt0 = (w & 1) * WNT;
    const int q = lane >> 2;

    cp_all<BW>(Bs1, Bf_ji, tid);
    cp_all<BW>(Bs2, Bf_kj, tid);
    CP_COMMIT();
    for (int i = tid; i < NRAD*EMB; i += 256) s_Wr[i] = g_Wr[i];
    stage_Ah<128>(m, m0, As, tid);
    CP_WAIT0();
    __syncthreads();

    float acc[2][WNT][4];

    // ======== phase 1: x_ji ========
    zero_acc<2*WNT>(&acc[0][0]);
    mainloop_full<128, NT, WNT>(As, Bs1, mp, nt0, lane, acc[0], acc[1]);
#pragma unroll
    for (int i = 0; i < 2; i++) {
        const size_t r_lo = m0 + mp*32 + i*16 + q;
        const size_t r_hi = r_lo + 8;
#pragma unroll
        for (int j = 0; j < WNT; j++) {
            const int col = (nt0 + j)*8 + (lane & 3)*2;
            const float2 bj = *(const float2*)&b_ji[col];
            float2 o0, o1;
            o0.x = silu_f(acc[i][j][0] + bj.x);
            o0.y = silu_f(acc[i][j][1] + bj.y);
            o1.x = silu_f(acc[i][j][2] + bj.x);
            o1.y = silu_f(acc[i][j][3] + bj.y);
            *(float2*)&out_ji[r_lo*128 + col] = o0;
            *(float2*)&out_ji[r_hi*128 + col] = o1;
        }
    }

    // ======== phase 2: tmp (kj * rbf_env) ========
    zero_acc<2*WNT>(&acc[0][0]);
    mainloop_full<128, NT, WNT>(As, Bs2, mp, nt0, lane, acc[0], acc[1]);
#pragma unroll
    for (int i = 0; i < 2; i++) {
        const size_t r_lo = m0 + mp*32 + i*16 + q;
        const size_t r_hi = r_lo + 8;
        float r6lo[NRAD], r6hi[NRAD];
#pragma unroll
        for (int l = 0; l < NRAD; l++) { r6lo[l] = rbf[r_lo*NRAD + l]; r6hi[l] = rbf[r_hi*NRAD + l]; }
#pragma unroll
        for (int j = 0; j < WNT; j++) {
            const int col = (nt0 + j)*8 + (lane & 3)*2;
            const float2 bj = *(const float2*)&b_kj[col];
            float e00=0.f,e01=0.f,e10=0.f,e11=0.f;
#pragma unroll
            for (int l = 0; l < NRAD; l++) {
                const float w0 = s_Wr[l*EMB + col], w1 = s_Wr[l*EMB + col + 1];
                e00 += r6lo[l]*w0; e01 += r6lo[l]*w1;
                e10 += r6hi[l]*w0; e11 += r6hi[l]*w1;
            }
            float2 o0, o1;
            o0.x = silu_f(acc[i][j][0] + bj.x) * e00;
            o0.y = silu_f(acc[i][j][1] + bj.y) * e01;
            o1.x = silu_f(acc[i][j][2] + bj.x) * e10;
            o1.y = silu_f(acc[i][j][3] + bj.y) * e11;
            *(float2*)&out_kj[r_lo*128 + col] = o0;
            *(float2*)&out_kj[r_hi*128 + col] = o1;
        }
    }
}

// ---------------- fused residual block (both B matrices resident) ---------------
__global__ __launch_bounds__(256, 2)
void resid_h(const float* __restrict__ X,
             const uint32_t* __restrict__ B1f, const float* __restrict__ b1,
             const uint32_t* __restrict__ B2f, const float* __restrict__ b2,
             float* __restrict__ out) {
    constexpr int NT = 16, WNT = 8, RW = 64, BW = 8192;
    extern __shared__ __align__(16) uint32_t dyn[];
    uint32_t* As  = dyn;
    uint32_t* Bs1 = dyn + 8192;
    uint32_t* Bs2 = dyn + 16384;

    const int tid = threadIdx.x, lane = tid & 31, w = tid >> 5;
    const size_t m0 = (size_t)blockIdx.x * 128;
    const int mp = w >> 1;
    const int nt0 = (w & 1) * WNT;
    const int q = lane >> 2;
    const int sw = q << 2;

    cp_all<BW>(Bs1, B1f, tid);
    cp_all<BW>(Bs2, B2f, tid);
    CP_COMMIT();
    stage_Ah<128>(X, m0, As, tid);
    CP_WAIT0();
    __syncthreads();

    float acc[2][WNT][4];
    zero_acc<2*WNT>(&acc[0][0]);
    mainloop_full<128, NT, WNT>(As, Bs1, mp, nt0, lane, acc[0], acc[1]);
    __syncthreads();   // partner n-half warp must finish reading As rows

    // epilogue1: h = silu(acc + b1) -> back into As (fp16 packed)
#pragma unroll
    for (int i = 0; i < 2; i++) {
        const int rl = mp*32 + i*16 + q;
#pragma unroll
        for (int j = 0; j < WNT; j++) {
            const int cj = (nt0 + j)*8 + (lane & 3)*2;
            const int cjp = cj >> 1;
            const float2 bj = *(const float2*)&b1[cj];
            As[rl*RW     + (cjp ^ sw)] = pack_h2(silu_f(acc[i][j][0] + bj.x),
                                                 silu_f(acc[i][j][1] + bj.y));
            As[(rl+8)*RW + (cjp ^ sw)] = pack_h2(silu_f(acc[i][j][2] + bj.x),
                                                 silu_f(acc[i][j][3] + bj.y));
        }
    }
    __syncthreads();

    zero_acc<2*WNT>(&acc[0][0]);
    mainloop_full<128, NT, WNT>(As, Bs2, mp, nt0, lane, acc[0], acc[1]);

    // epilogue2: out = X + silu(acc + b2)
#pragma unroll
    for (int i = 0; i < 2; i++) {
        const size_t r_lo = m0 + mp*32 + i*16 + q;
        const size_t r_hi = r_lo + 8;
#pragma unroll
        for (int j = 0; j < WNT; j++) {
            const int col = (nt0 + j)*8 + (lane & 3)*2;
            const float2 bj = *(const float2*)&b2[col];
            const float2 xl = *(const float2*)&X[r_lo*128 + col];
            const float2 xh = *(const float2*)&X[r_hi*128 + col];
            float2 o0, o1;
            o0.x = xl.x + silu_f(acc[i][j][0] + bj.x);
            o0.y = xl.y + silu_f(acc[i][j][1] + bj.y);
            o1.x = xh.x + silu_f(acc[i][j][2] + bj.x);
            o1.y = xh.y + silu_f(acc[i][j][3] + bj.y);
            *(float2*)&out[r_lo*128 + col] = o0;
            *(float2*)&out[r_hi*128 + col] = o1;
        }
    }
}

// ---------------- triplet kernel (unchanged, passes) ---------------------------
__global__ __launch_bounds__(256)
void triplet_kernel(const float* __restrict__ sbf,
                    const int* __restrict__ src_idx,
                    const int* __restrict__ dst_idx,
                    const float* __restrict__ W1,
                    const float* __restrict__ W2) {
    __shared__ float sbf_s[16*NSR];
    __shared__ float W1s[NSR*BASIS];
    __shared__ __align__(16) float W2s[BASIS*INT_EMB];
    __shared__ float t8[16][BASIS];

    const int tid = threadIdx.x;
    for (int i = tid; i < NSR*BASIS; i += 256) W1s[i] = W1[i];
    for (int i = tid; i < BASIS*INT_EMB; i += 256) W2s[i] = W2[i];

    const int ngroups = T_TRIP / 16;
    const int half = tid >> 4;
    const int l16  = tid & 15;

    for (int g = blockIdx.x; g < ngroups; g += gridDim.x) {
        const size_t base = (size_t)g * (16*NSR);
        for (int i = tid; i < 16*NSR; i += 256) sbf_s[i] = sbf[base + i];
        __syncthreads();

        if (tid < 128) {
            int tt = tid >> 3, j = tid & 7;
            float s = 0.f;
#pragma unroll
            for (int r = 0; r < NSR; r++) s += sbf_s[tt*NSR + r] * W1s[r*BASIS + j];
            t8[tt][j] = s;
        }
        __syncthreads();

        const int t = g*16 + half;
        const int src = src_idx[t];
        const int dst = dst_idx[t];

        float4 a = {0.f, 0.f, 0.f, 0.f};
#pragma unroll
        for (int j = 0; j < BASIS; j++) {
            const float tv = t8[half][j];
            const float4 w = *(const float4*)&W2s[j*INT_EMB + l16*4];
            a.x += tv*w.x; a.y += tv*w.y; a.z += tv*w.z; a.w += tv*w.w;
        }
        const float4 xk = *(const float4*)(g_xkj2 + (size_t)src*INT_EMB + l16*4);
        a.x *= xk.x; a.y *= xk.y; a.z *= xk.z; a.w *= xk.w;

        atomicAdd((float4*)(g_agg + (size_t)dst*INT_EMB + l16*4), a);
        __syncthreads();
    }
}

// ---------------- host launcher ----------------------------------------------
extern "C" void kernel_launch(void* const* d_in, const int* in_sizes, int n_in,
                              void* d_out, int out_size) {
    const float* m       = (const float*)d_in[0];
    const float* rbf     = (const float*)d_in[1];
    const float* sbf     = (const float*)d_in[2];
    const int*   src_idx = (const int*)d_in[3];
    const int*   dst_idx = (const int*)d_in[4];
    const float* W_rbf1  = (const float*)d_in[5];
    const float* W_rbf2  = (const float*)d_in[6];
    const float* W_sbf1  = (const float*)d_in[7];
    const float* W_sbf2  = (const float*)d_in[8];
    const float* W_ji    = (const float*)d_in[9];
    const float* b_ji    = (const float*)d_in[10];
    const float* W_kj    = (const float*)d_in[11];
    const float* b_kj    = (const float*)d_in[12];
    const float* W_down  = (const float*)d_in[13];
    const float* W_up    = (const float*)d_in[14];
    const float* Wb1     = (const float*)d_in[15];
    const float* bb1     = (const float*)d_in[16];
    const float* Wb2     = (const float*)d_in[17];
    const float* bb2     = (const float*)d_in[18];
    const float* W_final = (const float*)d_in[19];
    const float* b_final = (const float*)d_in[20];
    const float* Wa1     = (const float*)d_in[21];
    const float* ba1     = (const float*)d_in[22];
    const float* Wa2     = (const float*)d_in[23];
    const float* ba2     = (const float*)d_in[24];
    float* out = (float*)d_out;

    float *p_xji, *p_tmp, *p_upd, *p_xkj2, *p_agg;
    uint32_t* p_Bh;
    cudaGetSymbolAddress((void**)&p_xji,  g_xji);
    cudaGetSymbolAddress((void**)&p_tmp,  g_tmp);
    cudaGetSymbolAddress((void**)&p_upd,  g_upd);
    cudaGetSymbolAddress((void**)&p_xkj2, g_xkj2);
    cudaGetSymbolAddress((void**)&p_agg,  g_agg);
    cudaGetSymbolAddress((void**)&p_Bh,   g_Bh);

    const int GB = E_EDGES / 128;     // 2048
    // dyn smem (u32 words * 4)
    const int SM_TWO_B    = (8192*3)*4;                 // 98304: As + 2 B mats
    const int SM_N128K128 = (8192 + 8192)*4;            // 65536
    const int SM_N64K128  = (8192 + 4096)*4;            // 49152
    const int SM_N128K64  = (4096 + 4096)*4;            // 32768

    cudaFuncSetAttribute((const void*)gemm2_h, cudaFuncAttributeMaxDynamicSharedMemorySize, SM_TWO_B);
    cudaFuncSetAttribute((const void*)gemm_h<128,128,false,true >, cudaFuncAttributeMaxDynamicSharedMemorySize, SM_N128K128);
    cudaFuncSetAttribute((const void*)gemm_h<64 ,128,false,false>, cudaFuncAttributeMaxDynamicSharedMemorySize, SM_N64K128);
    cudaFuncSetAttribute((const void*)gemm_h<128,64 ,false,true >, cudaFuncAttributeMaxDynamicSharedMemorySize, SM_N128K64);
    cudaFuncSetAttribute((const void*)resid_h, cudaFuncAttributeMaxDynamicSharedMemorySize, SM_TWO_B);

    // ---- launch order: my #4 = gemm2_h (overall #6 for ncu -s 5 -c 1) ----
    stage_Bh<<<64, 128>>>(W_ji, p_Bh + OFF_JI, 128, 128);             // 1
    stage_Bh<<<64, 128>>>(W_kj, p_Bh + OFF_KJ, 128, 128);             // 2
    fuse_wr_kernel<<<3, 256>>>(W_rbf1, W_rbf2);                       // 3

    // x_ji & tmp in one pass (shared A staging)                      // 4 <- profiled
    gemm2_h<<<GB,256,SM_TWO_B>>>(m, p_Bh + OFF_JI, p_Bh + OFF_KJ,
                                 b_ji, b_kj, rbf, p_xji, p_tmp);

    zero_agg_kernel<<<(E_EDGES*INT_EMB/4)/256, 256>>>();              // 5
    stage_Bh<<<32, 128>>>(W_down, p_Bh + OFF_DOWN, 128, 64);          // 6
    stage_Bh<<<32, 128>>>(W_up,    p_Bh + OFF_UP,   64 , 128);
    stage_Bh<<<64, 128>>>(Wb1,     p_Bh + OFF_B1,   128, 128);
    stage_Bh<<<64, 128>>>(Wb2,     p_Bh + OFF_B2,   128, 128);
    stage_Bh<<<64, 128>>>(W_final, p_Bh + OFF_FIN,  128, 128);
    stage_Bh<<<64, 128>>>(Wa1,           p_Bh + OFF_A10, 128, 128);
    stage_Bh<<<64, 128>>>(Wa2,           p_Bh + OFF_A20, 128, 128);
    stage_Bh<<<64, 128>>>(Wa1 + 128*128, p_Bh + OFF_A11, 128, 128);
    stage_Bh<<<64, 128>>>(Wa2 + 128*128, p_Bh + OFF_A21, 128, 128);

    // x_kj2 = silu(tmp @ W_down)
    gemm_h<64 ,128,false,false><<<GB,256,SM_N64K128>>>(p_tmp, p_Bh + OFF_DOWN, nullptr, nullptr, nullptr, p_xkj2);

    // triplet message + segment sum
    triplet_kernel<<<4096, 256>>>(sbf, src_idx, dst_idx, W_sbf1, W_sbf2);

    // upd = x_ji + silu(agg @ W_up)
    gemm_h<128,64 ,false,true ><<<GB,256,SM_N128K64>>>(p_agg, p_Bh + OFF_UP, nullptr, p_xji, nullptr, p_upd);
    // residual-before (N_BEFORE=1), in-place
    resid_h<<<GB,256,SM_TWO_B>>>(p_upd, p_Bh + OFF_B1, bb1, p_Bh + OFF_B2, bb2, p_upd);
    // final: out = m + silu(upd @ W_final + b_final)
    gemm_h<128,128,false,true ><<<GB,256,SM_N128K128>>>(p_upd, p_Bh + OFF_FIN, b_final, m, nullptr, out);
    // residual-after (N_AFTER=2), in-place on out
    resid_h<<<GB,256,SM_TWO_B>>>(out, p_Bh + OFF_A10, ba1,       p_Bh + OFF_A20, ba2,       out);
    resid_h<<<GB,256,SM_TWO_B>>>(out, p_Bh + OFF_A11, ba1 + 128, p_Bh + OFF_A21, ba2 + 128, out);
}

// round 17
// speedup vs baseline: 1.0145x; 1.0145x over previous
#include <cuda_runtime.h>
#include <cuda_fp16.h>
#include <cstdint>

typedef unsigned long long ull;

#define EMB 128
#define INT_EMB 64
#define NRAD 6
#define NSR 42
#define BASIS 8
#define E_EDGES 262144
#define T_TRIP 2097152

// ---------------- scratch (device globals) ------------------------------------
__device__ float g_Wr[NRAD*EMB];
__device__ uint32_t g_xji_h[(size_t)E_EDGES*64];   // x_ji fp16 pairs (64 MB)
__device__ uint32_t g_tmp_h[(size_t)E_EDGES*64];   // tmp  fp16 pairs (64 MB)
__device__ float    g_upd[(size_t)E_EDGES*EMB];    // fp32 (residual carrier)
__device__ uint32_t g_xkj2_h[(size_t)E_EDGES*32];  // x_kj2 fp16 pairs (32 MB)
__device__ float    g_agg[(size_t)E_EDGES*INT_EMB];
__device__ uint32_t g_Bh[81920];   // all weights, fp16 fragment layout (m16n8k16)

// B-frag offsets (u32 elements; 128x128 matrix = 8192 u32)
#define OFF_JI   0
#define OFF_KJ   8192
#define OFF_DOWN 16384
#define OFF_UP   20480
#define OFF_B1   24576
#define OFF_B2   32768
#define OFF_FIN  40960
#define OFF_A10  49152
#define OFF_A20  57344
#define OFF_A11  65536
#define OFF_A21  73728

// ---------------- helpers ------------------------------------------------------
__device__ __forceinline__ float silu_f(float x){ return x * (1.0f/(1.0f + __expf(-x))); }
__device__ __forceinline__ uint32_t pack_h2(float lo, float hi){
    __half2 h = __floats2half2_rn(lo, hi);
    return *(uint32_t*)&h;
}
__device__ __forceinline__ float2 unpack_h2(uint32_t v){
    return __half22float2(*(__half2*)&v);
}
__device__ __forceinline__ void mma_f16(float* c, const uint32_t* a, const uint32_t* b){
    asm volatile("mma.sync.aligned.m16n8k16.row.col.f32.f16.f16.f32 "
        "{%0,%1,%2,%3}, {%4,%5,%6,%7}, {%8,%9}, {%0,%1,%2,%3};"
        : "+f"(c[0]), "+f"(c[1]), "+f"(c[2]), "+f"(c[3])
        : "r"(a[0]), "r"(a[1]), "r"(a[2]), "r"(a[3]), "r"(b[0]), "r"(b[1]));
}

// ---------------- K0: fuse W_rbf1 @ W_rbf2 -> g_Wr ----------------------------
__global__ void fuse_wr_kernel(const float* __restrict__ W1, const float* __restrict__ W2) {
    int i = blockIdx.x * blockDim.x + threadIdx.x;
    if (i < NRAD * EMB) {
        int r = i / EMB, n = i % EMB;
        float s = 0.f;
#pragma unroll
        for (int b = 0; b < BASIS; b++) s += W1[r*BASIS + b] * W2[b*EMB + n];
        g_Wr[i] = s;
    }
}

// ---------------- zero g_agg --------------------------------------------------
__global__ void zero_agg_kernel() {
    size_t i = (size_t)blockIdx.x * blockDim.x + threadIdx.x;
    float4 z = {0.f, 0.f, 0.f, 0.f};
    ((float4*)g_agg)[i] = z;
}

// ---------------- B fragment precompute (fp16 m16n8k16 layout) ------------------
__global__ void stage_Bh(const float* __restrict__ W, uint32_t* __restrict__ out,
                         int K, int N) {
    int i = blockIdx.x * 128 + threadIdx.x;
    if (i >= (K/2)*N) return;
    int kp = i / N, n = i % N;
    int k = kp * 2;
    uint32_t h = pack_h2(W[(size_t)k*N + n], W[(size_t)(k+1)*N + n]);
    int NT = N/8;
    int s = k >> 4, kk = k & 15;
    int rg = kk >> 3, lp = (kk & 7) >> 1;
    int lane = ((n & 7) << 2) | lp;
    int nt = n >> 3;
    out[((s*NT + nt)*32 + lane)*2 + rg] = h;
}

// ---------------- A staging ----------------------------------------------------
// fp32 source -> fp16 pairs, XOR-swizzled
template<int K>
__device__ __forceinline__ void stage_Ah(const float* __restrict__ A, size_t m0,
                                         uint32_t* __restrict__ As, int tid) {
    constexpr int QPR = K/4, RW = K/2;
    for (int i = tid; i < 128*QPR; i += 256) {
        int row = i / QPR, q4 = i % QPR;
        const float4 a4 = *(const float4*)&A[(m0+row)*K + q4*4];
        uint2 t;
        t.x = pack_h2(a4.x, a4.y);
        t.y = pack_h2(a4.z, a4.w);
        int c = (q4*2) ^ ((row & 7) << 2);
        *(uint2*)&As[row*RW + c] = t;
    }
}
// fp16-packed source (row-major u32 pairs) -> swizzled copy
template<int K>
__device__ __forceinline__ void stage_Ah16(const uint32_t* __restrict__ Ah, size_t m0,
                                           uint32_t* __restrict__ As, int tid) {
    constexpr int RW = K/2, GPR = RW/2;
    for (int i = tid; i < 128*GPR; i += 256) {
        int row = i / GPR, j = i % GPR;
        const uint2 t = *(const uint2*)&Ah[(m0+row)*RW + j*2];
        int c = (j*2) ^ ((row & 7) << 2);
        *(uint2*)&As[row*RW + c] = t;
    }
}

// ---------------- async full-matrix copy (gmem frags -> smem) -------------------
template<int WORDS>
__device__ __forceinline__ void cp_all(uint32_t* __restrict__ Bs,
                                       const uint32_t* __restrict__ Bf, int tid) {
    constexpr int NCP = (WORDS*4) / (256*16);
    const uint32_t sdst = (uint32_t)__cvta_generic_to_shared(Bs);
#pragma unroll
    for (int i = 0; i < NCP; i++) {
        const int off = (tid + i*256) * 16;
        asm volatile("cp.async.cg.shared.global [%0], [%1], 16;"
            :: "r"(sdst + (uint32_t)off), "l"((const char*)Bf + off) : "memory");
    }
}
#define CP_COMMIT() asm volatile("cp.async.commit_group;" ::: "memory")
#define CP_WAIT0()  asm volatile("cp.async.wait_group 0;" ::: "memory")

// ---------------- barrier-free mainloop ----------------------------------------
template<int K, int NT, int WNT>
__device__ __forceinline__ void mainloop_full(const uint32_t* __restrict__ As,
                                              const uint32_t* __restrict__ Bs,
                                              int mp, int nt0, int lane,
                                              float (*acc0)[4], float (*acc1)[4]) {
    constexpr int KS = K/16, RW = K/2;
    const int q = lane >> 2, sw = q << 2;
    const int rowA0 = (mp*32 + q) * RW;
    const int rowA1 = rowA0 + 16*RW;
#pragma unroll
    for (int s = 0; s < KS; s++) {
        const int cb = s*8 + (lane & 3);
        uint32_t a[2][4];
        a[0][0] = As[rowA0        + (cb ^ sw)];
        a[0][1] = As[rowA0 + 8*RW + (cb ^ sw)];
        a[0][2] = As[rowA0        + ((cb+4) ^ sw)];
        a[0][3] = As[rowA0 + 8*RW + ((cb+4) ^ sw)];
        a[1][0] = As[rowA1        + (cb ^ sw)];
        a[1][1] = As[rowA1 + 8*RW + (cb ^ sw)];
        a[1][2] = As[rowA1        + ((cb+4) ^ sw)];
        a[1][3] = As[rowA1 + 8*RW + ((cb+4) ^ sw)];
#pragma unroll
        for (int j = 0; j < WNT; j++) {
            uint2 b = *(const uint2*)&Bs[((s*NT + nt0 + j)*32 + lane)*2];
            mma_f16(acc0[j], a[0], (const uint32_t*)&b);
            mma_f16(acc1[j], a[1], (const uint32_t*)&b);
        }
    }
}
template<int W4>
__device__ __forceinline__ void zero_acc(float (*acc)[4]) {
#pragma unroll
    for (int i = 0; i < W4; i++)
#pragma unroll
        for (int e = 0; e < 4; e++) acc[i][e] = 0.f;
}

// ---------------- generic fused GEMM -------------------------------------------
// A_H16: A source is fp16-packed; OUT_H16: write fp16 pairs; RES_H16: res is fp16.
template<int N, int K, bool ADD_RES, bool A_H16, bool OUT_H16, bool RES_H16>
__global__ __launch_bounds__(256, 2)
void gemm_h(const void* __restrict__ Ain, const uint32_t* __restrict__ Bf,
            const float* __restrict__ bias, const void* __restrict__ resin,
            void* __restrict__ outv) {
    constexpr int NT = N/8, WNT = NT/2;
    constexpr int BW = (K/16)*NT*64;
    extern __shared__ __align__(16) uint32_t dyn[];
    uint32_t* As = dyn;
    uint32_t* Bs = dyn + 128*(K/2);

    const int tid = threadIdx.x, lane = tid & 31, w = tid >> 5;
    const size_t m0 = (size_t)blockIdx.x * 128;
    const int mp = w >> 1;
    const int nt0 = (w & 1) * WNT;
    const int q = lane >> 2;

    cp_all<BW>(Bs, Bf, tid);
    CP_COMMIT();
    if (A_H16) stage_Ah16<K>((const uint32_t*)Ain, m0, As, tid);
    else       stage_Ah<K>((const float*)Ain, m0, As, tid);
    CP_WAIT0();
    __syncthreads();

    float acc[2][WNT][4];
    zero_acc<2*WNT>(&acc[0][0]);
    mainloop_full<K, NT, WNT>(As, Bs, mp, nt0, lane, acc[0], acc[1]);

#pragma unroll
    for (int i = 0; i < 2; i++) {
        const size_t r_lo = m0 + mp*32 + i*16 + q;
        const size_t r_hi = r_lo + 8;
#pragma unroll
        for (int j = 0; j < WNT; j++) {
            const int col = (nt0 + j)*8 + (lane & 3)*2;
            float2 bj = make_float2(0.f, 0.f);
            if (bias) bj = *(const float2*)&bias[col];
            float v00 = silu_f(acc[i][j][0] + bj.x);
            float v01 = silu_f(acc[i][j][1] + bj.y);
            float v10 = silu_f(acc[i][j][2] + bj.x);
            float v11 = silu_f(acc[i][j][3] + bj.y);
            if (ADD_RES) {
                if (RES_H16) {
                    const uint32_t* res = (const uint32_t*)resin;
                    const float2 rl = unpack_h2(res[r_lo*(N/2) + (col>>1)]);
                    const float2 rh = unpack_h2(res[r_hi*(N/2) + (col>>1)]);
                    v00 += rl.x; v01 += rl.y; v10 += rh.x; v11 += rh.y;
                } else {
                    const float* res = (const float*)resin;
                    const float2 rl = *(const float2*)&res[r_lo*N + col];
                    const float2 rh = *(const float2*)&res[r_hi*N + col];
                    v00 += rl.x; v01 += rl.y; v10 += rh.x; v11 += rh.y;
                }
            }
            if (OUT_H16) {
                uint32_t* out = (uint32_t*)outv;
                out[r_lo*(N/2) + (col>>1)] = pack_h2(v00, v01);
                out[r_hi*(N/2) + (col>>1)] = pack_h2(v10, v11);
            } else {
                float* out = (float*)outv;
                float2 o0; o0.x = v00; o0.y = v01;
                float2 o1; o1.x = v10; o1.y = v11;
                *(float2*)&out[r_lo*N + col] = o0;
                *(float2*)&out[r_hi*N + col] = o1;
            }
        }
    }
}

// ---------------- fused ji+kj kernel (fp16 outputs) -----------------------------
__global__ __launch_bounds__(256, 2)
void gemm2_h(const float* __restrict__ m,
             const uint32_t* __restrict__ Bf_ji, const uint32_t* __restrict__ Bf_kj,
             const float* __restrict__ b_ji, const float* __restrict__ b_kj,
             const float* __restrict__ rbf,
             uint32_t* __restrict__ out_ji, uint32_t* __restrict__ out_kj) {
    constexpr int NT = 16, WNT = 8, BW = 8192;
    extern __shared__ __align__(16) uint32_t dyn[];
    uint32_t* As  = dyn;
    uint32_t* Bs1 = dyn + 8192;
    uint32_t* Bs2 = dyn + 16384;
    __shared__ float s_Wr[NRAD*EMB];

    const int tid = threadIdx.x, lane = tid & 31, w = tid >> 5;
    const size_t m0 = (size_t)blockIdx.x * 128;
    const int mp = w >> 1;
    const int nt0 = (w & 1) * WNT;
    const int q = lane >> 2;

    cp_all<BW>(Bs1, Bf_ji, tid);
    cp_all<BW>(Bs2, Bf_kj, tid);
    CP_COMMIT();
    for (int i = tid; i < NRAD*EMB; i += 256) s_Wr[i] = g_Wr[i];
    stage_Ah<128>(m, m0, As, tid);
    CP_WAIT0();
    __syncthreads();

    float acc[2][WNT][4];

    // ======== phase 1: x_ji (fp16 out) ========
    zero_acc<2*WNT>(&acc[0][0]);
    mainloop_full<128, NT, WNT>(As, Bs1, mp, nt0, lane, acc[0], acc[1]);
#pragma unroll
    for (int i = 0; i < 2; i++) {
        const size_t r_lo = m0 + mp*32 + i*16 + q;
        const size_t r_hi = r_lo + 8;
#pragma unroll
        for (int j = 0; j < WNT; j++) {
            const int col = (nt0 + j)*8 + (lane & 3)*2;
            const float2 bj = *(const float2*)&b_ji[col];
            out_ji[r_lo*64 + (col>>1)] = pack_h2(silu_f(acc[i][j][0] + bj.x),
                                                 silu_f(acc[i][j][1] + bj.y));
            out_ji[r_hi*64 + (col>>1)] = pack_h2(silu_f(acc[i][j][2] + bj.x),
                                                 silu_f(acc[i][j][3] + bj.y));
        }
    }

    // ======== phase 2: tmp = silu(m@Wkj+b)*env (fp16 out) ========
    zero_acc<2*WNT>(&acc[0][0]);
    mainloop_full<128, NT, WNT>(As, Bs2, mp, nt0, lane, acc[0], acc[1]);
#pragma unroll
    for (int i = 0; i < 2; i++) {
        const size_t r_lo = m0 + mp*32 + i*16 + q;
        const size_t r_hi = r_lo + 8;
        float r6lo[NRAD], r6hi[NRAD];
#pragma unroll
        for (int l = 0; l < NRAD; l++) { r6lo[l] = rbf[r_lo*NRAD + l]; r6hi[l] = rbf[r_hi*NRAD + l]; }
#pragma unroll
        for (int j = 0; j < WNT; j++) {
            const int col = (nt0 + j)*8 + (lane & 3)*2;
            const float2 bj = *(const float2*)&b_kj[col];
            float e00=0.f,e01=0.f,e10=0.f,e11=0.f;
#pragma unroll
            for (int l = 0; l < NRAD; l++) {
                const float w0 = s_Wr[l*EMB + col], w1 = s_Wr[l*EMB + col + 1];
                e00 += r6lo[l]*w0; e01 += r6lo[l]*w1;
                e10 += r6hi[l]*w0; e11 += r6hi[l]*w1;
            }
            out_kj[r_lo*64 + (col>>1)] = pack_h2(silu_f(acc[i][j][0] + bj.x) * e00,
                                                 silu_f(acc[i][j][1] + bj.y) * e01);
            out_kj[r_hi*64 + (col>>1)] = pack_h2(silu_f(acc[i][j][2] + bj.x) * e10,
                                                 silu_f(acc[i][j][3] + bj.y) * e11);
        }
    }
}

// ---------------- fused residual block (fp32 in/out) ----------------------------
__global__ __launch_bounds__(256, 2)
void resid_h(const float* __restrict__ X,
             const uint32_t* __restrict__ B1f, const float* __restrict__ b1,
             const uint32_t* __restrict__ B2f, const float* __restrict__ b2,
             float* __restrict__ out) {
    constexpr int NT = 16, WNT = 8, RW = 64, BW = 8192;
    extern __shared__ __align__(16) uint32_t dyn[];
    uint32_t* As  = dyn;
    uint32_t* Bs1 = dyn + 8192;
    uint32_t* Bs2 = dyn + 16384;

    const int tid = threadIdx.x, lane = tid & 31, w = tid >> 5;
    const size_t m0 = (size_t)blockIdx.x * 128;
    const int mp = w >> 1;
    const int nt0 = (w & 1) * WNT;
    const int q = lane >> 2;
    const int sw = q << 2;

    cp_all<BW>(Bs1, B1f, tid);
    cp_all<BW>(Bs2, B2f, tid);
    CP_COMMIT();
    stage_Ah<128>(X, m0, As, tid);
    CP_WAIT0();
    __syncthreads();

    float acc[2][WNT][4];
    zero_acc<2*WNT>(&acc[0][0]);
    mainloop_full<128, NT, WNT>(As, Bs1, mp, nt0, lane, acc[0], acc[1]);
    __syncthreads();

    // epilogue1: h = silu(acc + b1) -> back into As (fp16 packed)
#pragma unroll
    for (int i = 0; i < 2; i++) {
        const int rl = mp*32 + i*16 + q;
#pragma unroll
        for (int j = 0; j < WNT; j++) {
            const int cj = (nt0 + j)*8 + (lane & 3)*2;
            const int cjp = cj >> 1;
            const float2 bj = *(const float2*)&b1[cj];
            As[rl*RW     + (cjp ^ sw)] = pack_h2(silu_f(acc[i][j][0] + bj.x),
                                                 silu_f(acc[i][j][1] + bj.y));
            As[(rl+8)*RW + (cjp ^ sw)] = pack_h2(silu_f(acc[i][j][2] + bj.x),
                                                 silu_f(acc[i][j][3] + bj.y));
        }
    }
    __syncthreads();

    zero_acc<2*WNT>(&acc[0][0]);
    mainloop_full<128, NT, WNT>(As, Bs2, mp, nt0, lane, acc[0], acc[1]);

    // epilogue2: out = X + silu(acc + b2)
#pragma unroll
    for (int i = 0; i < 2; i++) {
        const size_t r_lo = m0 + mp*32 + i*16 + q;
        const size_t r_hi = r_lo + 8;
#pragma unroll
        for (int j = 0; j < WNT; j++) {
            const int col = (nt0 + j)*8 + (lane & 3)*2;
            const float2 bj = *(const float2*)&b2[col];
            const float2 xl = *(const float2*)&X[r_lo*128 + col];
            const float2 xh = *(const float2*)&X[r_hi*128 + col];
            float2 o0, o1;
            o0.x = xl.x + silu_f(acc[i][j][0] + bj.x);
            o0.y = xl.y + silu_f(acc[i][j][1] + bj.y);
            o1.x = xh.x + silu_f(acc[i][j][2] + bj.x);
            o1.y = xh.y + silu_f(acc[i][j][3] + bj.y);
            *(float2*)&out[r_lo*128 + col] = o0;
            *(float2*)&out[r_hi*128 + col] = o1;
        }
    }
}

// ---------------- triplet kernel (xkj2 now fp16) --------------------------------
__global__ __launch_bounds__(256)
void triplet_kernel(const float* __restrict__ sbf,
                    const int* __restrict__ src_idx,
                    const int* __restrict__ dst_idx,
                    const float* __restrict__ W1,
                    const float* __restrict__ W2) {
    __shared__ float sbf_s[16*NSR];
    __shared__ float W1s[NSR*BASIS];
    __shared__ __align__(16) float W2s[BASIS*INT_EMB];
    __shared__ float t8[16][BASIS];

    const int tid = threadIdx.x;
    for (int i = tid; i < NSR*BASIS; i += 256) W1s[i] = W1[i];
    for (int i = tid; i < BASIS*INT_EMB; i += 256) W2s[i] = W2[i];

    const int ngroups = T_TRIP / 16;
    const int half = tid >> 4;
    const int l16  = tid & 15;

    for (int g = blockIdx.x; g < ngroups; g += gridDim.x) {
        const size_t base = (size_t)g * (16*NSR);
        for (int i = tid; i < 16*NSR; i += 256) sbf_s[i] = sbf[base + i];
        __syncthreads();

        if (tid < 128) {
            int tt = tid >> 3, j = tid & 7;
            float s = 0.f;
#pragma unroll
            for (int r = 0; r < NSR; r++) s += sbf_s[tt*NSR + r] * W1s[r*BASIS + j];
            t8[tt][j] = s;
        }
        __syncthreads();

        const int t = g*16 + half;
        const int src = src_idx[t];
        const int dst = dst_idx[t];

        float4 a = {0.f, 0.f, 0.f, 0.f};
#pragma unroll
        for (int j = 0; j < BASIS; j++) {
            const float tv = t8[half][j];
            const float4 w = *(const float4*)&W2s[j*INT_EMB + l16*4];
            a.x += tv*w.x; a.y += tv*w.y; a.z += tv*w.z; a.w += tv*w.w;
        }
        const uint2 xk2 = *(const uint2*)(g_xkj2_h + (size_t)src*32 + l16*2);
        const float2 xlo = unpack_h2(xk2.x);
        const float2 xhi = unpack_h2(xk2.y);
        a.x *= xlo.x; a.y *= xlo.y; a.z *= xhi.x; a.w *= xhi.y;

        atomicAdd((float4*)(g_agg + (size_t)dst*INT_EMB + l16*4), a);
        __syncthreads();
    }
}

// ---------------- host launcher ----------------------------------------------
extern "C" void kernel_launch(void* const* d_in, const int* in_sizes, int n_in,
                              void* d_out, int out_size) {
    const float* m       = (const float*)d_in[0];
    const float* rbf     = (const float*)d_in[1];
    const float* sbf     = (const float*)d_in[2];
    const int*   src_idx = (const int*)d_in[3];
    const int*   dst_idx = (const int*)d_in[4];
    const float* W_rbf1  = (const float*)d_in[5];
    const float* W_rbf2  = (const float*)d_in[6];
    const float* W_sbf1  = (const float*)d_in[7];
    const float* W_sbf2  = (const float*)d_in[8];
    const float* W_ji    = (const float*)d_in[9];
    const float* b_ji    = (const float*)d_in[10];
    const float* W_kj    = (const float*)d_in[11];
    const float* b_kj    = (const float*)d_in[12];
    const float* W_down  = (const float*)d_in[13];
    const float* W_up    = (const float*)d_in[14];
    const float* Wb1     = (const float*)d_in[15];
    const float* bb1     = (const float*)d_in[16];
    const float* Wb2     = (const float*)d_in[17];
    const float* bb2     = (const float*)d_in[18];
    const float* W_final = (const float*)d_in[19];
    const float* b_final = (const float*)d_in[20];
    const float* Wa1     = (const float*)d_in[21];
    const float* ba1     = (const float*)d_in[22];
    const float* Wa2     = (const float*)d_in[23];
    const float* ba2     = (const float*)d_in[24];
    float* out = (float*)d_out;

    float *p_upd, *p_agg;
    uint32_t *p_xji_h, *p_tmp_h, *p_xkj2_h, *p_Bh;
    cudaGetSymbolAddress((void**)&p_xji_h,  g_xji_h);
    cudaGetSymbolAddress((void**)&p_tmp_h,  g_tmp_h);
    cudaGetSymbolAddress((void**)&p_upd,    g_upd);
    cudaGetSymbolAddress((void**)&p_xkj2_h, g_xkj2_h);
    cudaGetSymbolAddress((void**)&p_agg,    g_agg);
    cudaGetSymbolAddress((void**)&p_Bh,     g_Bh);

    const int GB = E_EDGES / 128;     // 2048
    const int SM_TWO_B    = (8192*3)*4;       // 98304
    const int SM_N128K128 = (8192 + 8192)*4;  // 65536
    const int SM_N64K128  = (8192 + 4096)*4;  // 49152
    const int SM_N128K64  = (4096 + 4096)*4;  // 32768

    // kernel instantiations
    auto k_down  = gemm_h<64 ,128,false,true ,true ,false>;  // A=tmp_h, out=xkj2_h
    auto k_up    = gemm_h<128,64 ,true ,false,false,true >;  // A=agg fp32, res=xji_h, out=upd fp32
    auto k_final = gemm_h<128,128,true ,false,false,false>;  // A=upd, res=m, out=out

    cudaFuncSetAttribute((const void*)gemm2_h, cudaFuncAttributeMaxDynamicSharedMemorySize, SM_TWO_B);
    cudaFuncSetAttribute((const void*)k_down,  cudaFuncAttributeMaxDynamicSharedMemorySize, SM_N64K128);
    cudaFuncSetAttribute((const void*)k_up,    cudaFuncAttributeMaxDynamicSharedMemorySize, SM_N128K64);
    cudaFuncSetAttribute((const void*)k_final, cudaFuncAttributeMaxDynamicSharedMemorySize, SM_N128K128);
    cudaFuncSetAttribute((const void*)resid_h, cudaFuncAttributeMaxDynamicSharedMemorySize, SM_TWO_B);

    // ---- launch order: my #4 = gemm2_h (overall #6 for ncu -s 5 -c 1) ----
    stage_Bh<<<64, 128>>>(W_ji, p_Bh + OFF_JI, 128, 128);             // 1
    stage_Bh<<<64, 128>>>(W_kj, p_Bh + OFF_KJ, 128, 128);             // 2
    fuse_wr_kernel<<<3, 256>>>(W_rbf1, W_rbf2);                       // 3

    // x_ji & tmp in one pass (fp16 outputs)                          // 4 <- profiled
    gemm2_h<<<GB,256,SM_TWO_B>>>(m, p_Bh + OFF_JI, p_Bh + OFF_KJ,
                                 b_ji, b_kj, rbf, p_xji_h, p_tmp_h);

    zero_agg_kernel<<<(E_EDGES*INT_EMB/4)/256, 256>>>();              // 5
    stage_Bh<<<32, 128>>>(W_down, p_Bh + OFF_DOWN, 128, 64);          // 6
    stage_Bh<<<32, 128>>>(W_up,    p_Bh + OFF_UP,   64 , 128);
    stage_Bh<<<64, 128>>>(Wb1,     p_Bh + OFF_B1,   128, 128);
    stage_Bh<<<64, 128>>>(Wb2,     p_Bh + OFF_B2,   128, 128);
    stage_Bh<<<64, 128>>>(W_final, p_Bh + OFF_FIN,  128, 128);
    stage_Bh<<<64, 128>>>(Wa1,           p_Bh + OFF_A10, 128, 128);
    stage_Bh<<<64, 128>>>(Wa2,           p_Bh + OFF_A20, 128, 128);
    stage_Bh<<<64, 128>>>(Wa1 + 128*128, p_Bh + OFF_A11, 128, 128);
    stage_Bh<<<64, 128>>>(Wa2 + 128*128, p_Bh + OFF_A21, 128, 128);

    // x_kj2 = silu(tmp @ W_down)  (fp16 in, fp16 out)
    k_down<<<GB,256,SM_N64K128>>>(p_tmp_h, p_Bh + OFF_DOWN, nullptr, nullptr, p_xkj2_h);

    // triplet message + segment sum
    triplet_kernel<<<4096, 256>>>(sbf, src_idx, dst_idx, W_sbf1, W_sbf2);

    // upd = x_ji + silu(agg @ W_up)  (res fp16)
    k_up<<<GB,256,SM_N128K64>>>(p_agg, p_Bh + OFF_UP, nullptr, p_xji_h, p_upd);
    // residual-before (N_BEFORE=1), in-place
    resid_h<<<GB,256,SM_TWO_B>>>(p_upd, p_Bh + OFF_B1, bb1, p_Bh + OFF_B2, bb2, p_upd);
    // final: out = m + silu(upd @ W_final + b_final)
    k_final<<<GB,256,SM_N128K128>>>(p_upd, p_Bh + OFF_FIN, b_final, m, out);
    // residual-after (N_AFTER=2), in-place on out
    resid_h<<<GB,256,SM_TWO_B>>>(out, p_Bh + OFF_A10, ba1,       p_Bh + OFF_A20, ba2,       out);
    resid_h<<<GB,256,SM_TWO_B>>>(out, p_Bh + OFF_A11, ba1 + 128, p_Bh + OFF_A21, ba2 + 128, out);
}